// round 14
// baseline (speedup 1.0000x reference)
#include <cuda_runtime.h>
#include <cuda_fp16.h>
#include <cstdint>

#define NUM_LEVELS 16
#define LOG2_HASHMAP 19
#define TABLE_SIZE (1u << LOG2_HASHMAP)
#define HASH_MASK (TABLE_SIZE - 1u)
#define N_QUERIES (1 << 20)

#define P1 2654435761u
#define P2 805459861u

// Dense cell tables for coarse levels 0..2
#define N0 4913      // 17^3
#define N1 35937     // 33^3
#define N2 274625    // 65^3
#define NCELLS (N0 + N1 + N2)
#define OFF0 0
#define OFF1 (N0 * 2)
#define OFF2 ((N0 + N1) * 2)

// repack only levels 3..15 (levels 0..2 served by g_cell)
#define SKIP_U2    (3 * TABLE_SIZE / 2)
#define CONV_U2    (NUM_LEVELS * TABLE_SIZE / 2)
#define CONV_COUNT (CONV_U2 - SKIP_U2)             // 3,407,872 uint2 slots
// 4 float4 (= 4 uint2 slots) per repack thread  (R11-validated form)
#define REPACK_THREADS (CONV_COUNT / 4)            // 851,968

__device__ uint32_t g_tab[NUM_LEVELS * TABLE_SIZE];
__device__ uint4 g_cell[NCELLS * 2];

__device__ __forceinline__ uint32_t pack_h2(float a, float b)
{
    __half2 h = __floats2half2_rn(a, b);
    return *reinterpret_cast<uint32_t*>(&h);
}

__device__ __forceinline__ float2 h2f(uint32_t u)
{
    __half2 h = *reinterpret_cast<__half2*>(&u);
    return __half22float2(h);
}

__device__ __forceinline__ uint32_t sel4(uint4 q, uint32_t s)
{
    uint32_t lo = (s & 1) ? q.y : q.x;
    uint32_t hi = (s & 1) ? q.w : q.z;
    return (s & 2) ? hi : lo;
}

// ── Prepass: cell build FIRST (latency-bound tail hidden), then 4x-ILP repack ──
__global__ void __launch_bounds__(256)
prepass_kernel(const float* __restrict__ emb)
{
    int i = blockIdx.x * blockDim.x + threadIdx.x;

    if (i < NCELLS) {
        // dense 8-corner cell build for levels 0..2 (gather-latency-bound)
        int j = i;
        int l, side, loc, off;
        if (j < N0)           { l = 0; side = 17; loc = j;            off = OFF0; }
        else if (j < N0 + N1) { l = 1; side = 33; loc = j - N0;       off = OFF1; }
        else                  { l = 2; side = 65; loc = j - N0 - N1;  off = OFF2; }
        int c2 = loc % side;
        int r  = loc / side;
        int c1 = r % side;
        int c0 = r / side;
        c0 -= 1; c1 -= 1; c2 -= 1;     // cell coords range [-1, res-1]

        const float2* lvl = reinterpret_cast<const float2*>(emb) + (size_t)l * TABLE_SIZE;
        uint32_t v[8];
#pragma unroll
        for (int o = 0; o < 8; o++) {
            uint32_t a = (uint32_t)(c0 + (o >> 2));
            uint32_t b = (uint32_t)(c1 + ((o >> 1) & 1));
            uint32_t c = (uint32_t)(c2 + (o & 1));
            uint32_t h = (a ^ (b * P1) ^ (c * P2)) & HASH_MASK;
            float2 e = __ldg(lvl + h);
            v[o] = pack_h2(e.x, e.y);
        }
        g_cell[off + loc * 2]     = make_uint4(v[0], v[1], v[2], v[3]);
        g_cell[off + loc * 2 + 1] = make_uint4(v[4], v[5], v[6], v[7]);
        return;
    }

    int k = i - NCELLS;
    if (k >= REPACK_THREADS) return;

    // fp16 repack, 4 float4 slots per thread (bandwidth-bound)
    int s = SKIP_U2 + k * 4;
    const float4* src = reinterpret_cast<const float4*>(emb) + s;
    float4 e0 = __ldg(src + 0);
    float4 e1 = __ldg(src + 1);
    float4 e2 = __ldg(src + 2);
    float4 e3 = __ldg(src + 3);
    uint4 pkA, pkB;
    pkA.x = pack_h2(e0.x, e0.y);  pkA.y = pack_h2(e0.z, e0.w);
    pkA.z = pack_h2(e1.x, e1.y);  pkA.w = pack_h2(e1.z, e1.w);
    pkB.x = pack_h2(e2.x, e2.y);  pkB.y = pack_h2(e2.z, e2.w);
    pkB.z = pack_h2(e3.x, e3.y);  pkB.w = pack_h2(e3.z, e3.w);
    uint4* dst = reinterpret_cast<uint4*>(reinterpret_cast<uint2*>(g_tab) + s);
    dst[0] = pkA;
    dst[1] = pkB;
}

// ── Fused encode kernel: champion body (dense l<3, parity hash l>=3, ACC2) ──
__global__ void __launch_bounds__(256)
encode_kernel(const float* __restrict__ inp,
              const int* __restrict__ bound_ptr,
              float* __restrict__ out)
{
    int tid = blockIdx.x * blockDim.x + threadIdx.x;
    int q = tid >> 4;
    int l = tid & 15;

    float inv_b = 1.0f / (float)(*bound_ptr);

    // channel permutation [2, 0, 1]
    float x0 = inp[3 * q + 2];
    float x1 = inp[3 * q + 0];
    float x2 = inp[3 * q + 1];

    float u0 = (x0 * inv_b + 1.0f) * 0.5f;
    float u1 = (x1 * inv_b + 1.0f) * 0.5f;
    float u2 = (x2 * inv_b + 1.0f) * 0.5f;

    float res = (float)(16u << l);

    float p0 = u0 * res - 0.5f;
    float p1 = u1 * res - 0.5f;
    float p2 = u2 * res - 0.5f;

    float f0 = floorf(p0), f1 = floorf(p1), f2 = floorf(p2);
    float fr0 = p0 - f0, fr1 = p1 - f1, fr2 = p2 - f2;

    int c0 = (int)f0, c1 = (int)f1, c2 = (int)f2;

    float w0a = 1.0f - fr0, w0b = fr0;
    float w1a = 1.0f - fr1, w1b = fr1;
    float w2a = 1.0f - fr2, w2b = fr2;

    float wc0 = w1a * w2a;
    float wc1 = w1a * w2b;
    float wc2 = w1b * w2a;
    float wc3 = w1b * w2b;

    float ox, oy;

    if (l < 3) {
        // ── dense path: 8 corners in one 32B cell entry (same 128B line) ──
        int side = (16 << l) + 1;
        int off = (l == 0) ? OFF0 : (l == 1) ? OFF1 : OFF2;
        int cell = ((c0 + 1) * side + (c1 + 1)) * side + (c2 + 1);
        const uint4* bp = g_cell + off + (size_t)cell * 2;
        uint4 A = __ldg(bp);       // dim0 = c0
        uint4 B = __ldg(bp + 1);   // dim0 = c0+1

        float2 f;
        float ax = 0.0f, ay = 0.0f, bx = 0.0f, by = 0.0f;
        f = h2f(A.x); ax = fmaf(wc0, f.x, ax); ay = fmaf(wc0, f.y, ay);
        f = h2f(A.y); ax = fmaf(wc1, f.x, ax); ay = fmaf(wc1, f.y, ay);
        f = h2f(A.z); ax = fmaf(wc2, f.x, ax); ay = fmaf(wc2, f.y, ay);
        f = h2f(A.w); ax = fmaf(wc3, f.x, ax); ay = fmaf(wc3, f.y, ay);
        f = h2f(B.x); bx = fmaf(wc0, f.x, bx); by = fmaf(wc0, f.y, by);
        f = h2f(B.y); bx = fmaf(wc1, f.x, bx); by = fmaf(wc1, f.y, by);
        f = h2f(B.z); bx = fmaf(wc2, f.x, bx); by = fmaf(wc2, f.y, by);
        f = h2f(B.w); bx = fmaf(wc3, f.x, bx); by = fmaf(wc3, f.y, by);
        ox = fmaf(w0a, ax, w0b * bx);
        oy = fmaf(w0a, ay, w0b * by);
    } else {
        // ── hash path: parity-divergent gather ──
        uint32_t hc0  = (uint32_t)c0;
        uint32_t hc0b = (uint32_t)(c0 + 1);
        uint32_t h1a = (uint32_t)c1 * P1;
        uint32_t h1b = (uint32_t)(c1 + 1) * P1;
        uint32_t h2a = (uint32_t)c2 * P2;
        uint32_t h2b = (uint32_t)(c2 + 1) * P2;

        uint32_t hjk0 = h1a ^ h2a;
        uint32_t hjk1 = h1a ^ h2b;
        uint32_t hjk2 = h1b ^ h2a;
        uint32_t hjk3 = h1b ^ h2b;

        uint32_t z0 = (hjk0 ^ hc0) & HASH_MASK;
        uint32_t z1 = (hjk1 ^ hc0) & HASH_MASK;
        uint32_t z2 = (hjk2 ^ hc0) & HASH_MASK;
        uint32_t z3 = (hjk3 ^ hc0) & HASH_MASK;

        const uint32_t* tab = g_tab + (size_t)l * TABLE_SIZE;

        ox = 0.0f; oy = 0.0f;

#define ACC(U0, U1, WC)                                            \
        {                                                          \
            float2 ea_ = h2f(U0);                                  \
            float2 eb_ = h2f(U1);                                  \
            ox = fmaf(WC, fmaf(w0a, ea_.x, w0b * eb_.x), ox);      \
            oy = fmaf(WC, fmaf(w0a, ea_.y, w0b * eb_.y), oy);      \
        }
#define ACC2(A, WX, WY, WC)                                        \
        {                                                          \
            float2 ea_ = h2f((A).x);                               \
            float2 eb_ = h2f((A).y);                               \
            ox = fmaf(WC, fmaf(WX, ea_.x, (WY) * eb_.x), ox);      \
            oy = fmaf(WC, fmaf(WX, ea_.y, (WY) * eb_.y), oy);      \
        }

        uint32_t par = (uint32_t)c0 & 3u;

        if ((par & 1u) == 0u) {
            // c0 even: one 8B aligned pair per combo; weight routing, no data SELs
            uint32_t s = ((uint32_t)(c0 ^ c1 ^ c2)) & 1u;
            float wA = s ? w0b : w0a;
            float wB = s ? w0a : w0b;
            uint2 A0 = __ldg((const uint2*)(tab + (z0 & ~1u)));
            uint2 A1 = __ldg((const uint2*)(tab + (z1 & ~1u)));
            uint2 A2 = __ldg((const uint2*)(tab + (z2 & ~1u)));
            uint2 A3 = __ldg((const uint2*)(tab + (z3 & ~1u)));
            ACC2(A0, wA, wB, wc0);
            ACC2(A1, wB, wA, wc1);
            ACC2(A2, wB, wA, wc2);
            ACC2(A3, wA, wB, wc3);
        } else if (par == 1u) {
            // c0 == 1 mod 4: one 16B aligned quad per combo
            uint4 Q0 = __ldg((const uint4*)(tab + (z0 & ~3u)));
            uint4 Q1 = __ldg((const uint4*)(tab + (z1 & ~3u)));
            uint4 Q2 = __ldg((const uint4*)(tab + (z2 & ~3u)));
            uint4 Q3 = __ldg((const uint4*)(tab + (z3 & ~3u)));
            ACC(sel4(Q0, z0 & 3u), sel4(Q0, (z0 & 3u) ^ 3u), wc0);
            ACC(sel4(Q1, z1 & 3u), sel4(Q1, (z1 & 3u) ^ 3u), wc1);
            ACC(sel4(Q2, z2 & 3u), sel4(Q2, (z2 & 3u) ^ 3u), wc2);
            ACC(sel4(Q3, z3 & 3u), sel4(Q3, (z3 & 3u) ^ 3u), wc3);
        } else {
            // c0 == 3 mod 4: two 4B loads per combo
            uint32_t y0 = (hjk0 ^ hc0b) & HASH_MASK;
            uint32_t y1 = (hjk1 ^ hc0b) & HASH_MASK;
            uint32_t y2 = (hjk2 ^ hc0b) & HASH_MASK;
            uint32_t y3 = (hjk3 ^ hc0b) & HASH_MASK;
            uint32_t a0 = __ldg(tab + z0);
            uint32_t a1 = __ldg(tab + z1);
            uint32_t a2 = __ldg(tab + z2);
            uint32_t a3 = __ldg(tab + z3);
            uint32_t b0 = __ldg(tab + y0);
            uint32_t b1 = __ldg(tab + y1);
            uint32_t b2 = __ldg(tab + y2);
            uint32_t b3 = __ldg(tab + y3);
            ACC(a0, b0, wc0);
            ACC(a1, b1, wc1);
            ACC(a2, b2, wc2);
            ACC(a3, b3, wc3);
        }
#undef ACC
#undef ACC2
    }

    float2* o = (float2*)(out + (size_t)q * (NUM_LEVELS * 2)) + l;
    *o = make_float2(ox, oy);
}

extern "C" void kernel_launch(void* const* d_in, const int* in_sizes, int n_in,
                              void* d_out, int out_size)
{
    const float* inp   = (const float*)d_in[0];
    const float* emb   = (const float*)d_in[1];
    const int*   bound = (const int*)d_in[2];
    float* out = (float*)d_out;

    // Prepass: cell build (first blocks, latency hidden) + fp16 repack
    int prep_total = NCELLS + REPACK_THREADS;
    prepass_kernel<<<(prep_total + 255) / 256, 256>>>(emb);

    // Fused encode: all 16 levels, one launch
    int total = N_QUERIES * NUM_LEVELS;
    encode_kernel<<<total / 256, 256>>>(inp, bound, out);
}

// round 15
// speedup vs baseline: 1.0569x; 1.0569x over previous
#include <cuda_runtime.h>
#include <cuda_fp16.h>
#include <cstdint>

#define NUM_LEVELS 16
#define LOG2_HASHMAP 19
#define TABLE_SIZE (1u << LOG2_HASHMAP)
#define HASH_MASK (TABLE_SIZE - 1u)
#define N_QUERIES (1 << 20)

#define P1 2654435761u
#define P2 805459861u

// Dense cell tables for coarse levels 0..2
#define N0 4913      // 17^3
#define N1 35937     // 33^3
#define N2 274625    // 65^3
#define NCELLS (N0 + N1 + N2)
#define OFF0 0
#define OFF1 (N0 * 2)
#define OFF2 ((N0 + N1) * 2)

// repack only levels 3..15 (levels 0..2 served by g_cell)
#define SKIP_U2    (3 * TABLE_SIZE / 2)
#define CONV_U2    (NUM_LEVELS * TABLE_SIZE / 2)
#define CONV_COUNT (CONV_U2 - SKIP_U2)             // 3,407,872 uint2 slots
// 4 float4 (= 4 uint2 slots) per repack thread  (R11-validated form)
#define REPACK_THREADS (CONV_COUNT / 4)            // 851,968

__device__ uint32_t g_tab[NUM_LEVELS * TABLE_SIZE];
__device__ uint4 g_cell[NCELLS * 2];

__device__ __forceinline__ uint32_t pack_h2(float a, float b)
{
    __half2 h = __floats2half2_rn(a, b);
    return *reinterpret_cast<uint32_t*>(&h);
}

__device__ __forceinline__ float2 h2f(uint32_t u)
{
    __half2 h = *reinterpret_cast<__half2*>(&u);
    return __half22float2(h);
}

__device__ __forceinline__ uint32_t sel4(uint4 q, uint32_t s)
{
    uint32_t lo = (s & 1) ? q.y : q.x;
    uint32_t hi = (s & 1) ? q.w : q.z;
    return (s & 2) ? hi : lo;
}

// ── Prepass (R11 form): 4x-ILP repack FIRST, cell build in tail blocks ──
__global__ void __launch_bounds__(256)
prepass_kernel(const float* __restrict__ emb)
{
    int i = blockIdx.x * blockDim.x + threadIdx.x;
    if (i < REPACK_THREADS) {
        // 4 consecutive float4 slots -> 4 uint2 stores; loads batched for MLP
        int s = SKIP_U2 + i * 4;
        const float4* src = reinterpret_cast<const float4*>(emb) + s;
        float4 e0 = __ldg(src + 0);
        float4 e1 = __ldg(src + 1);
        float4 e2 = __ldg(src + 2);
        float4 e3 = __ldg(src + 3);
        uint4 pkA, pkB;
        pkA.x = pack_h2(e0.x, e0.y);  pkA.y = pack_h2(e0.z, e0.w);
        pkA.z = pack_h2(e1.x, e1.y);  pkA.w = pack_h2(e1.z, e1.w);
        pkB.x = pack_h2(e2.x, e2.y);  pkB.y = pack_h2(e2.z, e2.w);
        pkB.z = pack_h2(e3.x, e3.y);  pkB.w = pack_h2(e3.z, e3.w);
        // s is a multiple of 4 (SKIP_U2 = 786432) -> 16B-aligned uint4 stores
        uint4* dst = reinterpret_cast<uint4*>(reinterpret_cast<uint2*>(g_tab) + s);
        dst[0] = pkA;
        dst[1] = pkB;
        return;
    }
    int j = i - REPACK_THREADS;
    if (j >= NCELLS) return;

    int l, side, loc, off;
    if (j < N0)           { l = 0; side = 17; loc = j;            off = OFF0; }
    else if (j < N0 + N1) { l = 1; side = 33; loc = j - N0;       off = OFF1; }
    else                  { l = 2; side = 65; loc = j - N0 - N1;  off = OFF2; }
    int c2 = loc % side;
    int r  = loc / side;
    int c1 = r % side;
    int c0 = r / side;
    c0 -= 1; c1 -= 1; c2 -= 1;     // cell coords range [-1, res-1]

    const float2* lvl = reinterpret_cast<const float2*>(emb) + (size_t)l * TABLE_SIZE;
    uint32_t v[8];
#pragma unroll
    for (int o = 0; o < 8; o++) {
        uint32_t a = (uint32_t)(c0 + (o >> 2));
        uint32_t b = (uint32_t)(c1 + ((o >> 1) & 1));
        uint32_t c = (uint32_t)(c2 + (o & 1));
        uint32_t h = (a ^ (b * P1) ^ (c * P2)) & HASH_MASK;
        float2 e = __ldg(lvl + h);
        v[o] = pack_h2(e.x, e.y);
    }
    g_cell[off + loc * 2]     = make_uint4(v[0], v[1], v[2], v[3]);
    g_cell[off + loc * 2 + 1] = make_uint4(v[4], v[5], v[6], v[7]);
}

// ── Fused encode kernel (R13 body): dense l<3, parity hash l>=3, ACC2 even path ──
__global__ void __launch_bounds__(256)
encode_kernel(const float* __restrict__ inp,
              const int* __restrict__ bound_ptr,
              float* __restrict__ out)
{
    int tid = blockIdx.x * blockDim.x + threadIdx.x;
    int q = tid >> 4;
    int l = tid & 15;

    float inv_b = 1.0f / (float)(*bound_ptr);

    // channel permutation [2, 0, 1]
    float x0 = inp[3 * q + 2];
    float x1 = inp[3 * q + 0];
    float x2 = inp[3 * q + 1];

    float u0 = (x0 * inv_b + 1.0f) * 0.5f;
    float u1 = (x1 * inv_b + 1.0f) * 0.5f;
    float u2 = (x2 * inv_b + 1.0f) * 0.5f;

    float res = (float)(16u << l);

    float p0 = u0 * res - 0.5f;
    float p1 = u1 * res - 0.5f;
    float p2 = u2 * res - 0.5f;

    float f0 = floorf(p0), f1 = floorf(p1), f2 = floorf(p2);
    float fr0 = p0 - f0, fr1 = p1 - f1, fr2 = p2 - f2;

    int c0 = (int)f0, c1 = (int)f1, c2 = (int)f2;

    float w0a = 1.0f - fr0, w0b = fr0;
    float w1a = 1.0f - fr1, w1b = fr1;
    float w2a = 1.0f - fr2, w2b = fr2;

    float wc0 = w1a * w2a;
    float wc1 = w1a * w2b;
    float wc2 = w1b * w2a;
    float wc3 = w1b * w2b;

    float ox, oy;

    if (l < 3) {
        // ── dense path: 8 corners in one 32B cell entry (same 128B line) ──
        int side = (16 << l) + 1;
        int off = (l == 0) ? OFF0 : (l == 1) ? OFF1 : OFF2;
        int cell = ((c0 + 1) * side + (c1 + 1)) * side + (c2 + 1);
        const uint4* bp = g_cell + off + (size_t)cell * 2;
        uint4 A = __ldg(bp);       // dim0 = c0
        uint4 B = __ldg(bp + 1);   // dim0 = c0+1

        float2 f;
        float ax = 0.0f, ay = 0.0f, bx = 0.0f, by = 0.0f;
        f = h2f(A.x); ax = fmaf(wc0, f.x, ax); ay = fmaf(wc0, f.y, ay);
        f = h2f(A.y); ax = fmaf(wc1, f.x, ax); ay = fmaf(wc1, f.y, ay);
        f = h2f(A.z); ax = fmaf(wc2, f.x, ax); ay = fmaf(wc2, f.y, ay);
        f = h2f(A.w); ax = fmaf(wc3, f.x, ax); ay = fmaf(wc3, f.y, ay);
        f = h2f(B.x); bx = fmaf(wc0, f.x, bx); by = fmaf(wc0, f.y, by);
        f = h2f(B.y); bx = fmaf(wc1, f.x, bx); by = fmaf(wc1, f.y, by);
        f = h2f(B.z); bx = fmaf(wc2, f.x, bx); by = fmaf(wc2, f.y, by);
        f = h2f(B.w); bx = fmaf(wc3, f.x, bx); by = fmaf(wc3, f.y, by);
        ox = fmaf(w0a, ax, w0b * bx);
        oy = fmaf(w0a, ay, w0b * by);
    } else {
        // ── hash path: parity-divergent gather ──
        uint32_t hc0  = (uint32_t)c0;
        uint32_t hc0b = (uint32_t)(c0 + 1);
        uint32_t h1a = (uint32_t)c1 * P1;
        uint32_t h1b = (uint32_t)(c1 + 1) * P1;
        uint32_t h2a = (uint32_t)c2 * P2;
        uint32_t h2b = (uint32_t)(c2 + 1) * P2;

        uint32_t hjk0 = h1a ^ h2a;
        uint32_t hjk1 = h1a ^ h2b;
        uint32_t hjk2 = h1b ^ h2a;
        uint32_t hjk3 = h1b ^ h2b;

        uint32_t z0 = (hjk0 ^ hc0) & HASH_MASK;
        uint32_t z1 = (hjk1 ^ hc0) & HASH_MASK;
        uint32_t z2 = (hjk2 ^ hc0) & HASH_MASK;
        uint32_t z3 = (hjk3 ^ hc0) & HASH_MASK;

        const uint32_t* tab = g_tab + (size_t)l * TABLE_SIZE;

        ox = 0.0f; oy = 0.0f;

#define ACC(U0, U1, WC)                                            \
        {                                                          \
            float2 ea_ = h2f(U0);                                  \
            float2 eb_ = h2f(U1);                                  \
            ox = fmaf(WC, fmaf(w0a, ea_.x, w0b * eb_.x), ox);      \
            oy = fmaf(WC, fmaf(w0a, ea_.y, w0b * eb_.y), oy);      \
        }
#define ACC2(A, WX, WY, WC)                                        \
        {                                                          \
            float2 ea_ = h2f((A).x);                               \
            float2 eb_ = h2f((A).y);                               \
            ox = fmaf(WC, fmaf(WX, ea_.x, (WY) * eb_.x), ox);      \
            oy = fmaf(WC, fmaf(WX, ea_.y, (WY) * eb_.y), oy);      \
        }

        uint32_t par = (uint32_t)c0 & 3u;

        if ((par & 1u) == 0u) {
            // c0 even: one 8B aligned pair per combo; weight routing, no data SELs
            uint32_t s = ((uint32_t)(c0 ^ c1 ^ c2)) & 1u;
            float wA = s ? w0b : w0a;
            float wB = s ? w0a : w0b;
            uint2 A0 = __ldg((const uint2*)(tab + (z0 & ~1u)));
            uint2 A1 = __ldg((const uint2*)(tab + (z1 & ~1u)));
            uint2 A2 = __ldg((const uint2*)(tab + (z2 & ~1u)));
            uint2 A3 = __ldg((const uint2*)(tab + (z3 & ~1u)));
            ACC2(A0, wA, wB, wc0);
            ACC2(A1, wB, wA, wc1);
            ACC2(A2, wB, wA, wc2);
            ACC2(A3, wA, wB, wc3);
        } else if (par == 1u) {
            // c0 == 1 mod 4: one 16B aligned quad per combo
            uint4 Q0 = __ldg((const uint4*)(tab + (z0 & ~3u)));
            uint4 Q1 = __ldg((const uint4*)(tab + (z1 & ~3u)));
            uint4 Q2 = __ldg((const uint4*)(tab + (z2 & ~3u)));
            uint4 Q3 = __ldg((const uint4*)(tab + (z3 & ~3u)));
            ACC(sel4(Q0, z0 & 3u), sel4(Q0, (z0 & 3u) ^ 3u), wc0);
            ACC(sel4(Q1, z1 & 3u), sel4(Q1, (z1 & 3u) ^ 3u), wc1);
            ACC(sel4(Q2, z2 & 3u), sel4(Q2, (z2 & 3u) ^ 3u), wc2);
            ACC(sel4(Q3, z3 & 3u), sel4(Q3, (z3 & 3u) ^ 3u), wc3);
        } else {
            // c0 == 3 mod 4: two 4B loads per combo
            uint32_t y0 = (hjk0 ^ hc0b) & HASH_MASK;
            uint32_t y1 = (hjk1 ^ hc0b) & HASH_MASK;
            uint32_t y2 = (hjk2 ^ hc0b) & HASH_MASK;
            uint32_t y3 = (hjk3 ^ hc0b) & HASH_MASK;
            uint32_t a0 = __ldg(tab + z0);
            uint32_t a1 = __ldg(tab + z1);
            uint32_t a2 = __ldg(tab + z2);
            uint32_t a3 = __ldg(tab + z3);
            uint32_t b0 = __ldg(tab + y0);
            uint32_t b1 = __ldg(tab + y1);
            uint32_t b2 = __ldg(tab + y2);
            uint32_t b3 = __ldg(tab + y3);
            ACC(a0, b0, wc0);
            ACC(a1, b1, wc1);
            ACC(a2, b2, wc2);
            ACC(a3, b3, wc3);
        }
#undef ACC
#undef ACC2
    }

    float2* o = (float2*)(out + (size_t)q * (NUM_LEVELS * 2)) + l;
    *o = make_float2(ox, oy);
}

extern "C" void kernel_launch(void* const* d_in, const int* in_sizes, int n_in,
                              void* d_out, int out_size)
{
    const float* inp   = (const float*)d_in[0];
    const float* emb   = (const float*)d_in[1];
    const int*   bound = (const int*)d_in[2];
    float* out = (float*)d_out;

    // Prepass: fp16 repack (4x ILP, first) + dense cell build (tail)
    int prep_total = REPACK_THREADS + NCELLS;
    prepass_kernel<<<(prep_total + 255) / 256, 256>>>(emb);

    // Fused encode: all 16 levels, one launch
    int total = N_QUERIES * NUM_LEVELS;
    encode_kernel<<<total / 256, 256>>>(inp, bound, out);
}